// round 5
// baseline (speedup 1.0000x reference)
#include <cuda_runtime.h>

#define NNODES 50000
#define NEDGES 800000
#define DIM 64
#define NSTEPS 5

typedef unsigned long long ull;

// Scratch state (allocation-free: __device__ globals), 16B-aligned.
__device__ __align__(16) float g_m[NNODES * DIM];     // messages m = h @ W
__device__ __align__(16) float g_agg[NNODES * DIM];   // gathered aggregate
__device__ __align__(16) float g_h[NNODES * DIM];     // hidden state ping buffer
__device__ int g_csr_src[NEDGES];                     // src ids grouped by dst
__device__ int g_row[NNODES + 1];                     // CSR row offsets (by dst)
__device__ int g_cnt[NNODES];                         // histogram / cursor

// ---------- packed f32x2 helpers ----------
__device__ __forceinline__ ull pack2(float lo, float hi) {
    ull r; asm("mov.b64 %0, {%1, %2};" : "=l"(r) : "f"(lo), "f"(hi)); return r;
}
__device__ __forceinline__ void fma2(ull& d, ull a, ull b) {
    asm("fma.rn.f32x2 %0, %1, %2, %0;" : "+l"(d) : "l"(a), "l"(b));
}
__device__ __forceinline__ float2 unpack2(ull v) {
    float2 r; asm("mov.b64 {%0, %1}, %2;" : "=f"(r.x), "=f"(r.y) : "l"(v)); return r;
}
__device__ __forceinline__ float sigf(float x) { return 1.0f / (1.0f + __expf(-x)); }
__device__ __forceinline__ float tanh_f(float x) {
    float t = __expf(-2.0f * fabsf(x));
    return copysignf((1.0f - t) / (1.0f + t), x);
}

// ======================================================================
// CSR build (once per launch): zero counts -> histogram -> scan -> place
// ======================================================================
__global__ void __launch_bounds__(1024) k_zero_cnt() {
    int i = blockIdx.x * 1024 + threadIdx.x;
    if (i < NNODES) g_cnt[i] = 0;
}

__global__ void __launch_bounds__(256) k_hist(const int* __restrict__ dst) {
    int e = blockIdx.x * 256 + threadIdx.x;
    if (e < NEDGES) atomicAdd(&g_cnt[__ldg(dst + e)], 1);   // no return -> RED
}

#define SCAN_PER_T 49   // 1024 * 49 = 50176 >= NNODES
__global__ void __launch_bounds__(1024) k_scan() {
    __shared__ int wsum[32];
    int tid = threadIdx.x;
    int lane = tid & 31, wid = tid >> 5;
    int base = tid * SCAN_PER_T;

    int loc[SCAN_PER_T];
    int s = 0;
    #pragma unroll
    for (int i = 0; i < SCAN_PER_T; i++) {
        int idx = base + i;
        int c = (idx < NNODES) ? g_cnt[idx] : 0;
        loc[i] = s;
        s += c;
    }
    // warp inclusive scan of per-thread totals
    int v = s;
    #pragma unroll
    for (int o = 1; o < 32; o <<= 1) {
        int t = __shfl_up_sync(0xFFFFFFFFu, v, o);
        if (lane >= o) v += t;
    }
    if (lane == 31) wsum[wid] = v;
    __syncthreads();
    if (wid == 0) {
        int w = wsum[lane];
        #pragma unroll
        for (int o = 1; o < 32; o <<= 1) {
            int t = __shfl_up_sync(0xFFFFFFFFu, w, o);
            if (lane >= o) w += t;
        }
        wsum[lane] = w;   // inclusive across warps
    }
    __syncthreads();
    int off = (wid > 0 ? wsum[wid - 1] : 0) + (v - s);  // exclusive thread offset
    #pragma unroll
    for (int i = 0; i < SCAN_PER_T; i++) {
        int idx = base + i;
        if (idx < NNODES) {
            g_row[idx] = off + loc[i];
            g_cnt[idx] = 0;             // reset as placement cursor
        }
    }
    if (tid == 0) g_row[NNODES] = NEDGES;
}

__global__ void __launch_bounds__(256) k_place(
    const int* __restrict__ src, const int* __restrict__ dst)
{
    int e = blockIdx.x * 256 + threadIdx.x;
    if (e >= NEDGES) return;
    int d = __ldg(dst + e);
    int pos = g_row[d] + atomicAdd(&g_cnt[d], 1);
    g_csr_src[pos] = __ldg(src + e);
}

// ======================================================================
// K1: m = h_in @ W. 2 threads per node (32 cols each) -> 16 acc regs,
// much better occupancy than 1 thread/node @112 regs.
// ======================================================================
__global__ void __launch_bounds__(256) k_transform(
    const float* __restrict__ x, const float* __restrict__ W, int first)
{
    __shared__ __align__(16) float Ws[DIM * DIM];
    int tid = threadIdx.x;
    #pragma unroll
    for (int i = tid; i < DIM * DIM / 4; i += 256)
        ((float4*)Ws)[i] = __ldg(((const float4*)W) + i);
    __syncthreads();

    int t = blockIdx.x * 256 + tid;
    int n = t >> 1;
    if (n >= NNODES) return;
    int jh = t & 1;                      // column half: jh*32 .. jh*32+31

    const float* hin = first ? x : g_h;

    ull acc[16];
    #pragma unroll
    for (int i = 0; i < 16; i++) acc[i] = 0ULL;

    const float4* hr = (const float4*)(hin + (size_t)n * DIM);
    #pragma unroll 4
    for (int kk = 0; kk < 16; kk++) {
        float4 hv = __ldg(hr + kk);
        float hvals[4] = {hv.x, hv.y, hv.z, hv.w};
        #pragma unroll
        for (int u = 0; u < 4; u++) {
            int k = kk * 4 + u;
            ull hx = pack2(hvals[u], hvals[u]);
            const ulonglong2* wrow = (const ulonglong2*)(Ws + k * DIM + jh * 32);
            #pragma unroll
            for (int j = 0; j < 8; j++) {
                ulonglong2 w = wrow[j];
                fma2(acc[2 * j],     hx, w.x);
                fma2(acc[2 * j + 1], hx, w.y);
            }
        }
    }

    float4* mout = (float4*)(g_m + (size_t)n * DIM + jh * 32);
    #pragma unroll
    for (int j = 0; j < 8; j++) {
        float2 a = unpack2(acc[2 * j]);
        float2 b = unpack2(acc[2 * j + 1]);
        mout[j] = make_float4(a.x, a.y, b.x, b.y);
    }
}

// ======================================================================
// K2: gather-reduce. Warp per dst node; 16 lanes x float4 cover one
// m[src] row (256B = 2 L2 lines, coalesced); 2 edges per iteration;
// shfl_xor(16) combines the two halves. No atomics.
// ======================================================================
__global__ void __launch_bounds__(256) k_gather() {
    int warp = (blockIdx.x * 256 + threadIdx.x) >> 5;
    if (warp >= NNODES) return;
    int lane = threadIdx.x & 31;
    int half = lane >> 4, p = lane & 15;

    int beg = __ldg(&g_row[warp]);
    int end = __ldg(&g_row[warp + 1]);

    float4 acc = make_float4(0.f, 0.f, 0.f, 0.f);
    for (int i = beg + half; i < end; i += 2) {
        int s = __ldg(&g_csr_src[i]);
        float4 v = __ldg((const float4*)(g_m + (size_t)s * DIM) + p);
        acc.x += v.x; acc.y += v.y; acc.z += v.z; acc.w += v.w;
    }
    acc.x += __shfl_xor_sync(0xFFFFFFFFu, acc.x, 16);
    acc.y += __shfl_xor_sync(0xFFFFFFFFu, acc.y, 16);
    acc.z += __shfl_xor_sync(0xFFFFFFFFu, acc.z, 16);
    acc.w += __shfl_xor_sync(0xFFFFFFFFu, acc.w, 16);
    if (half == 0)
        ((float4*)(g_agg + (size_t)warp * DIM))[p] = acc;
}

// ======================================================================
// K3: GRU cell. 128 nodes / 512 threads per block (16 warps/SM) to halve
// weight-staging traffic and double latency hiding vs R3.
// ======================================================================
#define WPAD 240   // 192 cols -> 12 chunks of 16, each padded by 4
#define RPAD 65
#define GRU_NODES 128
#define SMEM_GRU ((2 * 64 * WPAD + 2 * GRU_NODES * RPAD + 2 * 192) * 4)

__global__ void __launch_bounds__(512) k_gru(
    const float* __restrict__ x,
    const float* __restrict__ wih, const float* __restrict__ whh,
    const float* __restrict__ bih, const float* __restrict__ bhh,
    float* __restrict__ dout, int first, int last)
{
    extern __shared__ __align__(16) float sm[];
    float* wiT = sm;                          // [64][WPAD]
    float* whT = wiT + 64 * WPAD;             // [64][WPAD]
    float* ms  = whT + 64 * WPAD;             // [128][RPAD]
    float* hs  = ms + GRU_NODES * RPAD;       // [128][RPAD]
    float* bi  = hs + GRU_NODES * RPAD;       // [192]
    float* bh  = bi + 192;                    // [192]

    int tid = threadIdx.x;
    const float* hin = first ? x : g_h;
    float* hout = last ? dout : g_h;

    // Transpose + pad weights into smem: wT[k][pad(j)] = w[j][k]
    for (int i = tid; i < 192 * 64; i += 512) {
        int j = i >> 6, k = i & 63;
        int jp = j + (j >> 4) * 4;
        wiT[k * WPAD + jp] = __ldg(wih + i);
        whT[k * WPAD + jp] = __ldg(whh + i);
    }
    if (tid < 192) { bi[tid] = __ldg(bih + tid); bh[tid] = __ldg(bhh + tid); }

    // Stage this block's node rows (agg and h), coalesced reads
    int nbase = blockIdx.x * GRU_NODES;
    for (int i = tid; i < GRU_NODES * DIM; i += 512) {
        int nl = i >> 6, k = i & 63;
        int n = nbase + nl;
        float mv = 0.f, hv = 0.f;
        if (n < NNODES) {
            mv = __ldg(g_agg + (size_t)n * DIM + k);
            hv = __ldg(hin + (size_t)n * DIM + k);
        }
        ms[nl * RPAD + k] = mv;
        hs[nl * RPAD + k] = hv;
    }
    __syncthreads();

    int nl = tid >> 2;     // local node 0..127
    int jc = tid & 3;      // column chunk: owns columns jc*16 .. jc*16+15
    int n = nbase + nl;

    ull acc[6][8];
    #pragma unroll
    for (int g = 0; g < 3; g++) {
        #pragma unroll
        for (int u = 0; u < 8; u++) {
            int j = g * 64 + jc * 16 + 2 * u;
            acc[g][u]     = pack2(bi[j], bi[j + 1]);
            acc[3 + g][u] = pack2(bh[j], bh[j + 1]);
        }
    }

    const float* wibase = wiT + jc * 20;
    const float* whbase = whT + jc * 20;

    #pragma unroll 4
    for (int k = 0; k < 64; k++) {
        float mk = ms[nl * RPAD + k];
        float hk = hs[nl * RPAD + k];
        ull m2 = pack2(mk, mk);
        ull h2 = pack2(hk, hk);
        const ulonglong2* wi = (const ulonglong2*)(wibase + k * WPAD);
        const ulonglong2* wh = (const ulonglong2*)(whbase + k * WPAD);
        #pragma unroll
        for (int g = 0; g < 3; g++) {
            #pragma unroll
            for (int q = 0; q < 4; q++) {
                ulonglong2 a = wi[g * 20 + q];
                ulonglong2 b = wh[g * 20 + q];
                fma2(acc[g][2 * q],         m2, a.x);
                fma2(acc[g][2 * q + 1],     m2, a.y);
                fma2(acc[3 + g][2 * q],     h2, b.x);
                fma2(acc[3 + g][2 * q + 1], h2, b.y);
            }
        }
    }

    if (n < NNODES) {
        float4 out[4];
        #pragma unroll
        for (int q = 0; q < 8; q++) {
            float2 ir = unpack2(acc[0][q]);
            float2 iz = unpack2(acc[1][q]);
            float2 in = unpack2(acc[2][q]);
            float2 hr = unpack2(acc[3][q]);
            float2 hz = unpack2(acc[4][q]);
            float2 hn = unpack2(acc[5][q]);
            int j = jc * 16 + 2 * q;
            float h0 = hs[nl * RPAD + j];
            float h1 = hs[nl * RPAD + j + 1];
            float r0 = sigf(ir.x + hr.x), r1 = sigf(ir.y + hr.y);
            float z0 = sigf(iz.x + hz.x), z1 = sigf(iz.y + hz.y);
            float n0 = tanh_f(in.x + r0 * hn.x), n1 = tanh_f(in.y + r1 * hn.y);
            ((float*)out)[2 * q]     = (1.0f - z0) * n0 + z0 * h0;
            ((float*)out)[2 * q + 1] = (1.0f - z1) * n1 + z1 * h1;
        }
        float4* op = (float4*)(hout + (size_t)n * DIM + jc * 16);
        #pragma unroll
        for (int q = 0; q < 4; q++) op[q] = out[q];
    }
}

// ======================================================================
extern "C" void kernel_launch(void* const* d_in, const int* in_sizes, int n_in,
                              void* d_out, int out_size)
{
    const float* x   = (const float*)d_in[0];
    const int*   ei  = (const int*)d_in[1];     // int32 (JAX x64 disabled)
    const float* W   = (const float*)d_in[2];
    const float* wih = (const float*)d_in[3];
    const float* whh = (const float*)d_in[4];
    const float* bih = (const float*)d_in[5];
    const float* bhh = (const float*)d_in[6];
    float*       out = (float*)d_out;

    const int* src = ei;
    const int* dst = ei + NEDGES;

    static int smem_set = 0;
    if (!smem_set) {
        cudaFuncSetAttribute(k_gru, cudaFuncAttributeMaxDynamicSharedMemorySize, SMEM_GRU);
        smem_set = 1;
    }

    // ---- CSR build (by dst), once per launch ----
    k_zero_cnt<<<(NNODES + 1023) / 1024, 1024>>>();
    k_hist<<<(NEDGES + 255) / 256, 256>>>(dst);
    k_scan<<<1, 1024>>>();
    k_place<<<(NEDGES + 255) / 256, 256>>>(src, dst);

    const int g_tr = (2 * NNODES + 255) / 256;            // 391
    const int g_ga = (NNODES * 32 + 255) / 256;           // 6250
    const int g_gr = (NNODES + GRU_NODES - 1) / GRU_NODES; // 391

    for (int l = 0; l < NSTEPS; l++) {
        int first = (l == 0);
        int last  = (l == NSTEPS - 1);
        k_transform<<<g_tr, 256>>>(x, W + (size_t)l * DIM * DIM, first);
        k_gather<<<g_ga, 256>>>();
        k_gru<<<g_gr, 512, SMEM_GRU>>>(x, wih, whh, bih, bhh, out, first, last);
    }
}